// round 14
// baseline (speedup 1.0000x reference)
#include <cuda_runtime.h>

#define B_   4096
#define T_   64
#define OBS_ 64
#define H_   64
#define A_   8
#define S_   201
#define G_   16
#define NTHR 256

typedef unsigned long long u64;
typedef unsigned int u32;

__device__ __forceinline__ u64 fma2(u64 a, u64 b, u64 c) {
    u64 d;
    asm("fma.rn.f32x2 %0, %1, %2, %3;" : "=l"(d) : "l"(a), "l"(b), "l"(c));
    return d;
}
__device__ __forceinline__ u64 pack2(float x, float y) {
    u64 d;
    asm("mov.b64 %0, {%1, %2};" : "=l"(d) : "r"(__float_as_uint(x)), "r"(__float_as_uint(y)));
    return d;
}
__device__ __forceinline__ float2 unpack2(u64 a) {
    u32 lo, hi;
    asm("mov.b64 {%0, %1}, %2;" : "=r"(lo), "=r"(hi) : "l"(a));
    float2 r; r.x = __uint_as_float(lo); r.y = __uint_as_float(hi);
    return r;
}

// XLA/Eigen f32 fast-tanh clone — decision-critical, validated since R3. DO NOT TOUCH.
__device__ __forceinline__ float tanh_xla(float x) {
    float xc = fminf(fmaxf(x, -7.90531110763549805f), 7.90531110763549805f);
    float x2 = xc * xc;
    float p = -2.76076847742355e-16f;
    p = __fmaf_rn(p, x2, 2.00018790482477e-13f);
    p = __fmaf_rn(p, x2, -8.60467152213735e-11f);
    p = __fmaf_rn(p, x2, 5.12229709037114e-08f);
    p = __fmaf_rn(p, x2, 1.48572235717979e-05f);
    p = __fmaf_rn(p, x2, 6.37261928875436e-04f);
    p = __fmaf_rn(p, x2, 4.89352455891786e-03f);
    float num = xc * p;
    float q = 1.19825839466702e-06f;
    q = __fmaf_rn(q, x2, 1.18534705686654e-04f);
    q = __fmaf_rn(q, x2, 2.26843463243900e-03f);
    q = __fmaf_rn(q, x2, 4.89352518554385e-03f);
    float r = __fdiv_rn(num, q);
    return (fabsf(x) < 0.0004f) ? x : r;
}

#define OFF_VAL ((size_t)B_ * T_ * A_)
#define OFF_STK (OFF_VAL + (size_t)T_ * B_)
#define OFF_PTR (OFF_STK + (size_t)B_ * S_ * H_)

// x-GEMM scratch: xacc[b][t][j] = sum_{k<64} x[b][t][k] * W1[j][k]  (exact FFMA chain)
__device__ float g_xacc[(size_t)B_ * T_ * H_];

// ===================== xgemm: [262144 x 64] @ x-half of W1 =====================
// 128 rows/block, W1 staged ONCE per block (kills the R13 134MB weight re-read),
// 8-row x 4-col register tile. Per-output chain: FFMA k=0..63 ascending from 0 —
// bit-identical to R13's xgemm chain.
#define XG_ROWS 128
#define XG_WST  68
#define XG_XST  136
#define XG_SMEM ((64 * XG_WST + 64 * XG_XST) * 4)

__global__ void __launch_bounds__(256) xgemm_kernel(
    const float* __restrict__ x, const float* __restrict__ W1,
    float* __restrict__ xacc)
{
    extern __shared__ float xsm[];
    float* Wx = xsm;                    // [k][j] stride 68
    float* xs = xsm + 64 * XG_WST;      // [k][r] stride 136

    const int tid = threadIdx.x;
    const size_t row0 = (size_t)blockIdx.x * XG_ROWS;

    // stage W1 x-half transposed (coalesced global reads)
    for (int i = tid; i < 4096; i += 256) {
        int k = i & 63, j = i >> 6;
        Wx[k * XG_WST + j] = W1[j * 128 + k];
    }
    // stage x transposed [k][r]
    for (int i4 = tid; i4 < (XG_ROWS * 64) / 4; i4 += 256) {
        int flat = i4 * 4;
        int r = flat >> 6, k4 = flat & 63;
        float4 v = *(const float4*)(x + (row0 + r) * 64 + k4);
        xs[(k4 + 0) * XG_XST + r] = v.x;
        xs[(k4 + 1) * XG_XST + r] = v.y;
        xs[(k4 + 2) * XG_XST + r] = v.z;
        xs[(k4 + 3) * XG_XST + r] = v.w;
    }
    __syncthreads();

    const int rg = tid & 15;   // rows 8*rg .. 8*rg+7
    const int cg = tid >> 4;   // cols 4*cg .. 4*cg+3

    u64 acc[16];               // [row-pair p][col c]
    #pragma unroll
    for (int i = 0; i < 16; ++i) acc[i] = 0ull;

    const float* xb = &xs[8 * rg];
    const float* wb = &Wx[4 * cg];
    #pragma unroll 4
    for (int k = 0; k < 64; ++k) {
        ulonglong2 xA = *(const ulonglong2*)(xb + k * XG_XST);      // {r0,r1},{r2,r3}
        ulonglong2 xB = *(const ulonglong2*)(xb + k * XG_XST + 4);  // {r4,r5},{r6,r7}
        float4 w = *(const float4*)(wb + k * XG_WST);
        u64 w0 = pack2(w.x, w.x), w1 = pack2(w.y, w.y);
        u64 w2 = pack2(w.z, w.z), w3 = pack2(w.w, w.w);
        acc[0]  = fma2(xA.x, w0, acc[0]);  acc[1]  = fma2(xA.x, w1, acc[1]);
        acc[2]  = fma2(xA.x, w2, acc[2]);  acc[3]  = fma2(xA.x, w3, acc[3]);
        acc[4]  = fma2(xA.y, w0, acc[4]);  acc[5]  = fma2(xA.y, w1, acc[5]);
        acc[6]  = fma2(xA.y, w2, acc[6]);  acc[7]  = fma2(xA.y, w3, acc[7]);
        acc[8]  = fma2(xB.x, w0, acc[8]);  acc[9]  = fma2(xB.x, w1, acc[9]);
        acc[10] = fma2(xB.x, w2, acc[10]); acc[11] = fma2(xB.x, w3, acc[11]);
        acc[12] = fma2(xB.y, w0, acc[12]); acc[13] = fma2(xB.y, w1, acc[13]);
        acc[14] = fma2(xB.y, w2, acc[14]); acc[15] = fma2(xB.y, w3, acc[15]);
    }

    #pragma unroll
    for (int p = 0; p < 4; ++p) {
        float2 u0 = unpack2(acc[p * 4 + 0]);
        float2 u1 = unpack2(acc[p * 4 + 1]);
        float2 u2 = unpack2(acc[p * 4 + 2]);
        float2 u3 = unpack2(acc[p * 4 + 3]);
        size_t rowA = row0 + 8 * rg + 2 * p;
        *(float4*)(xacc + rowA * 64 + 4 * cg)       = make_float4(u0.x, u1.x, u2.x, u3.x);
        *(float4*)(xacc + (rowA + 1) * 64 + 4 * cg) = make_float4(u0.y, u1.y, u2.y, u3.y);
    }
}

// ============================ scan kernel ============================
// shared memory layout (floats)
#define SM_W1C   0                       // [64][64]  c-half of W1, transposed [k][j]
#define SM_W2T   (SM_W1C + 4096)         // [64][64]
#define SM_WHT   (SM_W2T + 4096)         // [64][12]
#define SM_B1    (SM_WHT + 768)
#define SM_B2    (SM_B1 + 64)
#define SM_BH    (SM_B2 + 64)            // 12
#define SM_CT    (SM_BH + 12)            // [64][18]
#define SM_HT    (SM_CT + 1152)          // [64][18]
#define SM_PT    (SM_HT + 1152)          // [64][18]
#define SM_LS    (SM_PT + 1152)          // [16][4]
#define SM_INTS  (SM_LS + 64)            // ptrS(16) + wbits(112)
#define SMEM_BYTES ((SM_INTS + 128) * 4)

__global__ void __launch_bounds__(NTHR, 2) stacknet_kernel(
    const float* __restrict__ x,        const float* __restrict__ stack_in,
    const int*   __restrict__ ptr_in,
    const float* __restrict__ W1,  const float* __restrict__ b1,
    const float* __restrict__ W2,  const float* __restrict__ b2,
    const float* __restrict__ Ws,  const float* __restrict__ bsv,
    const float* __restrict__ Wp,  const float* __restrict__ bp,
    const float* __restrict__ Wv,  const float* __restrict__ bv,
    float* __restrict__ out)
{
    extern __shared__ float sm[];
    float* W1c  = sm + SM_W1C;
    float* W2t  = sm + SM_W2T;
    float* Wht  = sm + SM_WHT;
    float* b1s  = sm + SM_B1;
    float* b2s  = sm + SM_B2;
    float* bhs  = sm + SM_BH;
    float* CT   = sm + SM_CT;
    float* Ht   = sm + SM_HT;
    float* Pt   = sm + SM_PT;
    float* Ls   = sm + SM_LS;
    int*   ptrS  = (int*)(sm + SM_INTS);
    u32*   wbits = (u32*)(ptrS + 16);

    const int tid  = threadIdx.x;
    const int base = blockIdx.x * G_;

    for (int i = tid; i < 4096; i += NTHR) {            // c-half of W1 (k = 64..127)
        int k = i & 63, j = i >> 6;
        W1c[k * 64 + j] = W1[j * 128 + 64 + k];
    }
    for (int i = tid; i < 4096; i += NTHR) { int j = i >> 6, k = i & 63;  W2t[k * 64 + j] = W2[i]; }
    for (int i = tid; i < 192;  i += NTHR) { int h = i >> 6, k = i & 63;  Wht[k * 12 + h] = Ws[i]; }
    for (int i = tid; i < 512;  i += NTHR) { int h = 3 + (i >> 6), k = i & 63; Wht[k * 12 + h] = Wp[i]; }
    for (int i = tid; i < 64;   i += NTHR) { Wht[i * 12 + 11] = Wv[i]; }
    if (tid < 64) { b1s[tid] = b1[tid]; b2s[tid] = b2[tid]; }
    if (tid < 3)               bhs[tid] = bsv[tid];
    if (tid >= 3 && tid < 11)  bhs[tid] = bp[tid - 3];
    if (tid == 11)             bhs[11]  = bv[0];
    for (int i = tid; i < G_ * 7; i += NTHR) wbits[i] = 0;
    if (tid < G_) ptrS[tid] = ptr_in[base + tid];

    // matmul map: elem pair {2ep, 2ep+1}, col pair {2cp, 2cp+1}
    const int ep = tid & 7;
    const int cp = tid >> 3;
    // IO map: element e, segment seg (features seg*4..seg*4+3)
    const int e   = tid >> 4;
    const int seg = tid & 15;

    const size_t srow = (size_t)(base + e) * S_;
    const size_t xb0  = ((size_t)(base + 2 * ep)) * T_ * 64;
    const size_t xb1  = ((size_t)(base + 2 * ep + 1)) * T_ * 64;
    float* ostk = out + OFF_STK;

    // initial state
    float4 cr, pm4, pp4;
    float xa00, xa10, xa01, xa11;
    {
        int p0 = ptr_in[base + e];
        cr = *(const float4*)(stack_in + (srow + p0) * H_ + seg * 4);
        const float* cf = (const float*)&cr;
        #pragma unroll
        for (int i = 0; i < 4; ++i) CT[(seg * 4 + i) * 18 + e] = cf[i];
        xa00 = g_xacc[xb0 + 2 * cp];     xa10 = g_xacc[xb1 + 2 * cp];
        xa01 = g_xacc[xb0 + 2 * cp + 1]; xa11 = g_xacc[xb1 + 2 * cp + 1];
    }

    for (int t = 0; t < T_; ++t) {
        __syncthreads();   // A: CT(t)/ptrS/wbits/push-STG of t-1 visible

        const int p = ptrS[e];
        if (t + 1 < T_) {
            const int rm = p > 0 ? p - 1 : 0;
            const int rp = p + 1;
            const float* bm = ((wbits[e * 7 + (rm >> 5)] >> (rm & 31)) & 1u) ? ostk : stack_in;
            const float* bq = ((wbits[e * 7 + (rp >> 5)] >> (rp & 31)) & 1u) ? ostk : stack_in;
            pm4 = *(const float4*)(bm + (srow + rm) * H_ + seg * 4);
            pp4 = *(const float4*)(bq + (srow + rp) * H_ + seg * 4);
        }

        // ---- W1 (c-half): 2elem x 2col tile, paired input LDS.64, seeded by xacc ----
        u64 a0 = pack2(xa00, xa10);      // col 2cp:   lanes {e0, e1}
        u64 a1 = pack2(xa01, xa11);      // col 2cp+1
        {
            const float* inb = &CT[2 * ep];
            const float* wb  = &W1c[2 * cp];
            #pragma unroll 8
            for (int k = 0; k < 64; ++k) {
                u64 in = *(const u64*)(inb + k * 18);       // {e0,e1}
                float2 w = *(const float2*)(wb + k * 64);   // {w_j0, w_j1}
                a0 = fma2(in, pack2(w.x, w.x), a0);
                a1 = fma2(in, pack2(w.y, w.y), a1);
            }
        }
        if (t + 1 < T_) {
            xa00 = g_xacc[xb0 + (size_t)(t + 1) * 64 + 2 * cp];
            xa10 = g_xacc[xb1 + (size_t)(t + 1) * 64 + 2 * cp];
            xa01 = g_xacc[xb0 + (size_t)(t + 1) * 64 + 2 * cp + 1];
            xa11 = g_xacc[xb1 + (size_t)(t + 1) * 64 + 2 * cp + 1];
        }
        {
            float2 v0 = unpack2(a0), v1 = unpack2(a1);
            int j0 = 2 * cp, e0 = 2 * ep;
            Ht[j0 * 18 + e0]           = tanh_xla(v0.x + b1s[j0]);
            Ht[j0 * 18 + e0 + 1]       = tanh_xla(v0.y + b1s[j0]);
            Ht[(j0 + 1) * 18 + e0]     = tanh_xla(v1.x + b1s[j0 + 1]);
            Ht[(j0 + 1) * 18 + e0 + 1] = tanh_xla(v1.y + b1s[j0 + 1]);
        }
        __syncthreads();   // B: Ht ready

        // ---- W2: same tile, seed 0 ----
        a0 = 0ull; a1 = 0ull;
        {
            const float* inb = &Ht[2 * ep];
            const float* wb  = &W2t[2 * cp];
            #pragma unroll 8
            for (int k = 0; k < 64; ++k) {
                u64 in = *(const u64*)(inb + k * 18);
                float2 w = *(const float2*)(wb + k * 64);
                a0 = fma2(in, pack2(w.x, w.x), a0);
                a1 = fma2(in, pack2(w.y, w.y), a1);
            }
        }
        {
            float2 v0 = unpack2(a0), v1 = unpack2(a1);
            int j0 = 2 * cp, e0 = 2 * ep;
            Pt[j0 * 18 + e0]           = tanh_xla(v0.x + b2s[j0]);
            Pt[j0 * 18 + e0 + 1]       = tanh_xla(v0.y + b2s[j0]);
            Pt[(j0 + 1) * 18 + e0]     = tanh_xla(v1.x + b2s[j0 + 1]);
            Pt[(j0 + 1) * 18 + e0 + 1] = tanh_xla(v1.y + b2s[j0 + 1]);
        }
        __syncthreads();   // C: Pt ready

        // ---- heads: 192 dots of length 64, bias LAST (R3 order) ----
        if (tid < 192) {
            int ee = tid / 12, h = tid - 12 * ee;
            float acc = 0.0f;
            #pragma unroll 8
            for (int k = 0; k < 64; ++k) acc = __fmaf_rn(Pt[k * 18 + ee], Wht[k * 12 + h], acc);
            acc += bhs[h];
            if (h < 3)       Ls[ee * 4 + h] = acc;
            else if (h < 11) out[((size_t)(base + ee) * T_ + t) * A_ + (h - 3)] = acc;
            else             out[OFF_VAL + (size_t)t * B_ + (base + ee)] = acc;
        }
        __syncthreads();   // D: Ls ready

        // ---- replicated argmax + stack update + CT(t+1) (no barrier; A covers it) ----
        {
            float l0 = Ls[e * 4], l1 = Ls[e * 4 + 1], l2 = Ls[e * 4 + 2];
            int op = 0; float bst = l0;
            if (l1 > bst) { bst = l1; op = 1; }
            if (l2 > bst) { op = 2; }
            if (seg == 0) {
                int np = p + op - 1; np = np < 0 ? 0 : np;
                ptrS[e] = np;
                if (op == 2) wbits[e * 7 + (p >> 5)] |= (1u << (p & 31));
            }
            if (op == 2) {
                float pv[4];
                #pragma unroll
                for (int i = 0; i < 4; ++i) pv[i] = Pt[(seg * 4 + i) * 18 + e];
                *(float4*)(ostk + (srow + p) * H_ + seg * 4)
                    = make_float4(pv[0], pv[1], pv[2], pv[3]);
                cr = pp4;
            } else if (op == 0) {
                cr = pm4;
            }
            if (t + 1 < T_) {
                const float* cf = (const float*)&cr;
                #pragma unroll
                for (int i = 0; i < 4; ++i) CT[(seg * 4 + i) * 18 + e] = cf[i];
            }
        }
    }

    __syncthreads();   // ptrS writers (seg==0) != readers below
    if (tid < G_) out[OFF_PTR + base + tid] = (float)ptrS[tid];
    __syncthreads();

    for (int it = tid; it < G_ * S_; it += NTHR) {
        int ee = it / S_, rr = it - S_ * ee;
        if (!((wbits[ee * 7 + (rr >> 5)] >> (rr & 31)) & 1u)) {
            const float4* src = (const float4*)(stack_in + ((size_t)(base + ee) * S_ + rr) * H_);
            float4* dst = (float4*)(out + OFF_STK + ((size_t)(base + ee) * S_ + rr) * H_);
            #pragma unroll
            for (int q = 0; q < 16; ++q) dst[q] = src[q];
        }
    }
}

extern "C" void kernel_launch(void* const* d_in, const int* in_sizes, int n_in,
                              void* d_out, int out_size) {
    (void)in_sizes; (void)n_in; (void)out_size;
    cudaFuncSetAttribute(stacknet_kernel, cudaFuncAttributeMaxDynamicSharedMemorySize, SMEM_BYTES);
    cudaFuncSetAttribute(xgemm_kernel, cudaFuncAttributeMaxDynamicSharedMemorySize, XG_SMEM);
    const float* x        = (const float*)d_in[0];
    const float* stack_in = (const float*)d_in[1];
    const int*   ptrs     = (const int*)  d_in[2];
    const float* W1 = (const float*)d_in[3];  const float* b1 = (const float*)d_in[4];
    const float* W2 = (const float*)d_in[5];  const float* b2 = (const float*)d_in[6];
    const float* Ws = (const float*)d_in[7];  const float* bs = (const float*)d_in[8];
    const float* Wp = (const float*)d_in[9];  const float* bp = (const float*)d_in[10];
    const float* Wv = (const float*)d_in[11]; const float* bv = (const float*)d_in[12];
    float* out = (float*)d_out;

    float* xacc = nullptr;
    cudaGetSymbolAddress((void**)&xacc, g_xacc);

    xgemm_kernel<<<(B_ * T_) / XG_ROWS, 256, XG_SMEM>>>(x, W1, xacc);
    stacknet_kernel<<<B_ / G_, NTHR, SMEM_BYTES>>>(
        x, stack_in, ptrs, W1, b1, W2, b2, Ws, bs, Wp, bp, Wv, bv, out);
}

// round 15
// speedup vs baseline: 1.2167x; 1.2167x over previous
#include <cuda_runtime.h>

#define B_   4096
#define T_   64
#define OBS_ 64
#define H_   64
#define A_   8
#define S_   201
#define G_   16
#define NTHR 256

typedef unsigned long long u64;
typedef unsigned int u32;

__device__ __forceinline__ u64 fma2(u64 a, u64 b, u64 c) {
    u64 d;
    asm("fma.rn.f32x2 %0, %1, %2, %3;" : "=l"(d) : "l"(a), "l"(b), "l"(c));
    return d;
}
__device__ __forceinline__ u64 pack2(float x, float y) {
    u64 d;
    asm("mov.b64 %0, {%1, %2};" : "=l"(d) : "r"(__float_as_uint(x)), "r"(__float_as_uint(y)));
    return d;
}
__device__ __forceinline__ float2 unpack2(u64 a) {
    u32 lo, hi;
    asm("mov.b64 {%0, %1}, %2;" : "=r"(lo), "=r"(hi) : "l"(a));
    float2 r; r.x = __uint_as_float(lo); r.y = __uint_as_float(hi);
    return r;
}

// XLA/Eigen f32 fast-tanh clone — decision-critical, validated since R3. DO NOT TOUCH.
__device__ __forceinline__ float tanh_xla(float x) {
    float xc = fminf(fmaxf(x, -7.90531110763549805f), 7.90531110763549805f);
    float x2 = xc * xc;
    float p = -2.76076847742355e-16f;
    p = __fmaf_rn(p, x2, 2.00018790482477e-13f);
    p = __fmaf_rn(p, x2, -8.60467152213735e-11f);
    p = __fmaf_rn(p, x2, 5.12229709037114e-08f);
    p = __fmaf_rn(p, x2, 1.48572235717979e-05f);
    p = __fmaf_rn(p, x2, 6.37261928875436e-04f);
    p = __fmaf_rn(p, x2, 4.89352455891786e-03f);
    float num = xc * p;
    float q = 1.19825839466702e-06f;
    q = __fmaf_rn(q, x2, 1.18534705686654e-04f);
    q = __fmaf_rn(q, x2, 2.26843463243900e-03f);
    q = __fmaf_rn(q, x2, 4.89352518554385e-03f);
    float r = __fdiv_rn(num, q);
    return (fabsf(x) < 0.0004f) ? x : r;
}

#define OFF_VAL ((size_t)B_ * T_ * A_)
#define OFF_STK (OFF_VAL + (size_t)T_ * B_)
#define OFF_PTR (OFF_STK + (size_t)B_ * S_ * H_)

// x-GEMM scratch, laid out [t][b][j] so each scan block's per-step seeds are contiguous
__device__ float g_xacc[(size_t)T_ * B_ * H_];

// ===================== xgemm v3: [B*T x 64] @ x-half of W1 =====================
// 256 rows/block (grid 1024), W1 staged ONCE, x staged stride-68 (STS.128
// conflict-free), scalar row-broadcast reads. Per-output chain: FFMA k=0..63
// ascending from 0 — bit-identical to R13/R14 (tiling-independent).
#define XG_ROWS 256
#define XG_XST  68
#define XG_SMEM ((64 * 64 + XG_ROWS * XG_XST) * 4)

__global__ void __launch_bounds__(256) xgemm_kernel(
    const float* __restrict__ x, const float* __restrict__ W1,
    float* __restrict__ xacc)
{
    extern __shared__ float xsm[];
    float* Wx = xsm;                 // [k][j] stride 64
    float* xs = xsm + 64 * 64;       // [r][k] stride 68

    const int tid = threadIdx.x;
    const size_t row0 = (size_t)blockIdx.x * XG_ROWS;

    for (int i = tid; i < 4096; i += 256) {
        int k = i & 63, j = i >> 6;
        Wx[k * 64 + j] = W1[j * 128 + k];
    }
    for (int i4 = tid; i4 < (XG_ROWS * 64) / 4; i4 += 256) {
        int flat = i4 * 4;
        int r = flat >> 6, k4 = flat & 63;
        *(float4*)&xs[r * XG_XST + k4] = *(const float4*)(x + (row0 + r) * 64 + k4);
    }
    __syncthreads();

    const int rl0 = tid >> 3;   // 0..31
    const int oct = tid & 7;    // cols 8*oct .. 8*oct+7

    #pragma unroll 1
    for (int batch = 0; batch < XG_ROWS / 32; ++batch) {
        int r = batch * 32 + rl0;
        const float* xb = &xs[r * XG_XST];
        const float* wb = &Wx[8 * oct];
        u64 a0 = 0ull, a1 = 0ull, a2 = 0ull, a3 = 0ull;
        #pragma unroll 8
        for (int k = 0; k < 64; ++k) {
            float in = xb[k];
            u64 ax = pack2(in, in);
            ulonglong2 w01 = *(const ulonglong2*)(wb + k * 64);
            ulonglong2 w23 = *(const ulonglong2*)(wb + k * 64 + 4);
            a0 = fma2(ax, w01.x, a0); a1 = fma2(ax, w01.y, a1);
            a2 = fma2(ax, w23.x, a2); a3 = fma2(ax, w23.y, a3);
        }
        float2 u0 = unpack2(a0), u1 = unpack2(a1), u2 = unpack2(a2), u3 = unpack2(a3);
        size_t R = row0 + r;                       // R = b*T + t
        size_t b = R >> 6, t = R & 63;
        float* dst = xacc + (t * B_ + b) * 64 + 8 * oct;
        *(float4*)dst       = make_float4(u0.x, u0.y, u1.x, u1.y);
        *(float4*)(dst + 4) = make_float4(u2.x, u2.y, u3.x, u3.y);
    }
}

// ============================ scan kernel ============================
#define SM_W1C   0                       // [64][64] c-half of W1 [k][j]
#define SM_W2T   (SM_W1C + 4096)         // [64][64]
#define SM_WHT   (SM_W2T + 4096)         // [64][12]
#define SM_B1    (SM_WHT + 768)
#define SM_B2    (SM_B1 + 64)
#define SM_BH    (SM_B2 + 64)            // 12
#define SM_CT    (SM_BH + 12)            // [64][18] top, transposed
#define SM_XT    (SM_CT + 1152)          // [64][18] xacc seeds, transposed
#define SM_HT    (SM_XT + 1152)          // [64][18]
#define SM_PT    (SM_HT + 1152)          // [64][18]
#define SM_LS    (SM_PT + 1152)          // [16][4]
#define SM_INTS  (SM_LS + 64)            // ptrS(16) + wbits(112)
#define SMEM_BYTES ((SM_INTS + 128) * 4)

__global__ void __launch_bounds__(NTHR, 2) stacknet_kernel(
    const float* __restrict__ x,        const float* __restrict__ stack_in,
    const int*   __restrict__ ptr_in,
    const float* __restrict__ W1,  const float* __restrict__ b1,
    const float* __restrict__ W2,  const float* __restrict__ b2,
    const float* __restrict__ Ws,  const float* __restrict__ bsv,
    const float* __restrict__ Wp,  const float* __restrict__ bp,
    const float* __restrict__ Wv,  const float* __restrict__ bv,
    float* __restrict__ out)
{
    extern __shared__ float sm[];
    float* W1c  = sm + SM_W1C;
    float* W2t  = sm + SM_W2T;
    float* Wht  = sm + SM_WHT;
    float* b1s  = sm + SM_B1;
    float* b2s  = sm + SM_B2;
    float* bhs  = sm + SM_BH;
    float* CT   = sm + SM_CT;
    float* XT   = sm + SM_XT;
    float* Ht   = sm + SM_HT;
    float* Pt   = sm + SM_PT;
    float* Ls   = sm + SM_LS;
    int*   ptrS  = (int*)(sm + SM_INTS);
    u32*   wbits = (u32*)(ptrS + 16);

    const int tid  = threadIdx.x;
    const int base = blockIdx.x * G_;

    for (int i = tid; i < 4096; i += NTHR) {            // c-half of W1 (k = 64..127)
        int k = i & 63, j = i >> 6;
        W1c[k * 64 + j] = W1[j * 128 + 64 + k];
    }
    for (int i = tid; i < 4096; i += NTHR) { int j = i >> 6, k = i & 63;  W2t[k * 64 + j] = W2[i]; }
    for (int i = tid; i < 192;  i += NTHR) { int h = i >> 6, k = i & 63;  Wht[k * 12 + h] = Ws[i]; }
    for (int i = tid; i < 512;  i += NTHR) { int h = 3 + (i >> 6), k = i & 63; Wht[k * 12 + h] = Wp[i]; }
    for (int i = tid; i < 64;   i += NTHR) { Wht[i * 12 + 11] = Wv[i]; }
    if (tid < 64) { b1s[tid] = b1[tid]; b2s[tid] = b2[tid]; }
    if (tid < 3)               bhs[tid] = bsv[tid];
    if (tid >= 3 && tid < 11)  bhs[tid] = bp[tid - 3];
    if (tid == 11)             bhs[11]  = bv[0];
    for (int i = tid; i < G_ * 7; i += NTHR) wbits[i] = 0;
    if (tid < G_) ptrS[tid] = ptr_in[base + tid];

    // matmul map: elem pair {2ep,2ep+1}, col pair {2cp,2cp+1}
    const int ep = tid & 7;
    const int cp = tid >> 3;
    // IO map: element e, segment seg (features/cols seg*4..seg*4+3)
    const int e   = tid >> 4;
    const int seg = tid & 15;

    const size_t srow = (size_t)(base + e) * S_;
    float* ostk = out + OFF_STK;

    // initial state: top0 -> CT, xacc(t=0) -> XT (coalesced)
    float4 cr, pm4, pp4, xa4;
    {
        int p0 = ptr_in[base + e];
        cr = *(const float4*)(stack_in + (srow + p0) * H_ + seg * 4);
        const float* cf = (const float*)&cr;
        xa4 = *(const float4*)(g_xacc + (size_t)(base + e) * 64 + seg * 4);  // t=0
        const float* xf = (const float*)&xa4;
        #pragma unroll
        for (int i = 0; i < 4; ++i) {
            CT[(seg * 4 + i) * 18 + e] = cf[i];
            XT[(seg * 4 + i) * 18 + e] = xf[i];
        }
    }

    for (int t = 0; t < T_; ++t) {
        __syncthreads();   // A: CT/XT(t), ptrS/wbits, prev push STG visible

        const int p = ptrS[e];
        if (t + 1 < T_) {
            const int rm = p > 0 ? p - 1 : 0;
            const int rp = p + 1;
            const float* bm = ((wbits[e * 7 + (rm >> 5)] >> (rm & 31)) & 1u) ? ostk : stack_in;
            const float* bq = ((wbits[e * 7 + (rp >> 5)] >> (rp & 31)) & 1u) ? ostk : stack_in;
            pm4 = *(const float4*)(bm + (srow + rm) * H_ + seg * 4);
            pp4 = *(const float4*)(bq + (srow + rp) * H_ + seg * 4);
            // coalesced seed prefetch for t+1 ([t][b][j] layout)
            xa4 = *(const float4*)(g_xacc + ((size_t)(t + 1) * B_ + base + e) * 64 + seg * 4);
        }

        // ---- W1 (c-half): 2e x 2c tile, seeded from XT (R14-validated chain) ----
        u64 a0 = *(const u64*)&XT[(2 * cp) * 18 + 2 * ep];       // {xacc[e0][j0], xacc[e1][j0]}
        u64 a1 = *(const u64*)&XT[(2 * cp + 1) * 18 + 2 * ep];
        {
            const float* inb = &CT[2 * ep];
            const float* wb  = &W1c[2 * cp];
            #pragma unroll 8
            for (int k = 0; k < 64; ++k) {
                u64 in = *(const u64*)(inb + k * 18);       // {e0,e1}
                float2 w = *(const float2*)(wb + k * 64);
                a0 = fma2(in, pack2(w.x, w.x), a0);
                a1 = fma2(in, pack2(w.y, w.y), a1);
            }
        }
        {
            float2 v0 = unpack2(a0), v1 = unpack2(a1);
            int j0 = 2 * cp, e0 = 2 * ep;
            Ht[j0 * 18 + e0]           = tanh_xla(v0.x + b1s[j0]);
            Ht[j0 * 18 + e0 + 1]       = tanh_xla(v0.y + b1s[j0]);
            Ht[(j0 + 1) * 18 + e0]     = tanh_xla(v1.x + b1s[j0 + 1]);
            Ht[(j0 + 1) * 18 + e0 + 1] = tanh_xla(v1.y + b1s[j0 + 1]);
        }
        __syncthreads();   // B: Ht ready

        // ---- W2: same tile, seed 0 ----
        a0 = 0ull; a1 = 0ull;
        {
            const float* inb = &Ht[2 * ep];
            const float* wb  = &W2t[2 * cp];
            #pragma unroll 8
            for (int k = 0; k < 64; ++k) {
                u64 in = *(const u64*)(inb + k * 18);
                float2 w = *(const float2*)(wb + k * 64);
                a0 = fma2(in, pack2(w.x, w.x), a0);
                a1 = fma2(in, pack2(w.y, w.y), a1);
            }
        }
        {
            float2 v0 = unpack2(a0), v1 = unpack2(a1);
            int j0 = 2 * cp, e0 = 2 * ep;
            Pt[j0 * 18 + e0]           = tanh_xla(v0.x + b2s[j0]);
            Pt[j0 * 18 + e0 + 1]       = tanh_xla(v0.y + b2s[j0]);
            Pt[(j0 + 1) * 18 + e0]     = tanh_xla(v1.x + b2s[j0 + 1]);
            Pt[(j0 + 1) * 18 + e0 + 1] = tanh_xla(v1.y + b2s[j0 + 1]);
        }
        __syncthreads();   // C: Pt ready

        // ---- heads: 192 dots of length 64, bias LAST (R3 order) ----
        if (tid < 192) {
            int ee = tid / 12, h = tid - 12 * ee;
            float acc = 0.0f;
            #pragma unroll 8
            for (int k = 0; k < 64; ++k) acc = __fmaf_rn(Pt[k * 18 + ee], Wht[k * 12 + h], acc);
            acc += bhs[h];
            if (h < 3)       Ls[ee * 4 + h] = acc;
            else if (h < 11) out[((size_t)(base + ee) * T_ + t) * A_ + (h - 3)] = acc;
            else             out[OFF_VAL + (size_t)t * B_ + (base + ee)] = acc;
        }
        __syncthreads();   // D: Ls ready

        // ---- replicated argmax + stack update + CT/XT(t+1) ----
        {
            float l0 = Ls[e * 4], l1 = Ls[e * 4 + 1], l2 = Ls[e * 4 + 2];
            int op = 0; float bst = l0;
            if (l1 > bst) { bst = l1; op = 1; }
            if (l2 > bst) { op = 2; }
            if (seg == 0) {
                int np = p + op - 1; np = np < 0 ? 0 : np;
                ptrS[e] = np;
                if (op == 2) wbits[e * 7 + (p >> 5)] |= (1u << (p & 31));
            }
            if (op == 2) {
                float pv[4];
                #pragma unroll
                for (int i = 0; i < 4; ++i) pv[i] = Pt[(seg * 4 + i) * 18 + e];
                *(float4*)(ostk + (srow + p) * H_ + seg * 4)
                    = make_float4(pv[0], pv[1], pv[2], pv[3]);
                cr = pp4;
            } else if (op == 0) {
                cr = pm4;
            }
            if (t + 1 < T_) {
                const float* cf = (const float*)&cr;
                const float* xf = (const float*)&xa4;
                #pragma unroll
                for (int i = 0; i < 4; ++i) {
                    CT[(seg * 4 + i) * 18 + e] = cf[i];
                    XT[(seg * 4 + i) * 18 + e] = xf[i];
                }
            }
        }
    }

    __syncthreads();   // ptrS writers (seg==0) != readers below
    if (tid < G_) out[OFF_PTR + base + tid] = (float)ptrS[tid];
    __syncthreads();

    for (int it = tid; it < G_ * S_; it += NTHR) {
        int ee = it / S_, rr = it - S_ * ee;
        if (!((wbits[ee * 7 + (rr >> 5)] >> (rr & 31)) & 1u)) {
            const float4* src = (const float4*)(stack_in + ((size_t)(base + ee) * S_ + rr) * H_);
            float4* dst = (float4*)(out + OFF_STK + ((size_t)(base + ee) * S_ + rr) * H_);
            #pragma unroll
            for (int q = 0; q < 16; ++q) dst[q] = src[q];
        }
    }
}

extern "C" void kernel_launch(void* const* d_in, const int* in_sizes, int n_in,
                              void* d_out, int out_size) {
    (void)in_sizes; (void)n_in; (void)out_size;
    cudaFuncSetAttribute(stacknet_kernel, cudaFuncAttributeMaxDynamicSharedMemorySize, SMEM_BYTES);
    cudaFuncSetAttribute(xgemm_kernel, cudaFuncAttributeMaxDynamicSharedMemorySize, XG_SMEM);
    const float* x        = (const float*)d_in[0];
    const float* stack_in = (const float*)d_in[1];
    const int*   ptrs     = (const int*)  d_in[2];
    const float* W1 = (const float*)d_in[3];  const float* b1 = (const float*)d_in[4];
    const float* W2 = (const float*)d_in[5];  const float* b2 = (const float*)d_in[6];
    const float* Ws = (const float*)d_in[7];  const float* bs = (const float*)d_in[8];
    const float* Wp = (const float*)d_in[9];  const float* bp = (const float*)d_in[10];
    const float* Wv = (const float*)d_in[11]; const float* bv = (const float*)d_in[12];
    float* out = (float*)d_out;

    float* xacc = nullptr;
    cudaGetSymbolAddress((void**)&xacc, g_xacc);

    xgemm_kernel<<<(B_ * T_) / XG_ROWS, 256, XG_SMEM>>>(x, W1, xacc);
    stacknet_kernel<<<B_ / G_, NTHR, SMEM_BYTES>>>(
        x, stack_in, ptrs, W1, b1, W2, b2, Ws, bs, Wp, bp, Wv, bv, out);
}

// round 16
// speedup vs baseline: 1.7250x; 1.4178x over previous
#include <cuda_runtime.h>

#define B_   4096
#define T_   64
#define OBS_ 64
#define H_   64
#define A_   8
#define S_   201
#define G_   16
#define NTHR 256

typedef unsigned long long u64;
typedef unsigned int u32;

__device__ __forceinline__ u64 fma2(u64 a, u64 b, u64 c) {
    u64 d;
    asm("fma.rn.f32x2 %0, %1, %2, %3;" : "=l"(d) : "l"(a), "l"(b), "l"(c));
    return d;
}
__device__ __forceinline__ u64 pack2(float x, float y) {
    u64 d;
    asm("mov.b64 %0, {%1, %2};" : "=l"(d) : "r"(__float_as_uint(x)), "r"(__float_as_uint(y)));
    return d;
}
__device__ __forceinline__ float2 unpack2(u64 a) {
    u32 lo, hi;
    asm("mov.b64 {%0, %1}, %2;" : "=r"(lo), "=r"(hi) : "l"(a));
    float2 r; r.x = __uint_as_float(lo); r.y = __uint_as_float(hi);
    return r;
}

// XLA/Eigen f32 fast-tanh clone — decision-critical, validated since R3. DO NOT TOUCH.
__device__ __forceinline__ float tanh_xla(float x) {
    float xc = fminf(fmaxf(x, -7.90531110763549805f), 7.90531110763549805f);
    float x2 = xc * xc;
    float p = -2.76076847742355e-16f;
    p = __fmaf_rn(p, x2, 2.00018790482477e-13f);
    p = __fmaf_rn(p, x2, -8.60467152213735e-11f);
    p = __fmaf_rn(p, x2, 5.12229709037114e-08f);
    p = __fmaf_rn(p, x2, 1.48572235717979e-05f);
    p = __fmaf_rn(p, x2, 6.37261928875436e-04f);
    p = __fmaf_rn(p, x2, 4.89352455891786e-03f);
    float num = xc * p;
    float q = 1.19825839466702e-06f;
    q = __fmaf_rn(q, x2, 1.18534705686654e-04f);
    q = __fmaf_rn(q, x2, 2.26843463243900e-03f);
    q = __fmaf_rn(q, x2, 4.89352518554385e-03f);
    float r = __fdiv_rn(num, q);
    return (fabsf(x) < 0.0004f) ? x : r;
}

#define OFF_VAL ((size_t)B_ * T_ * A_)
#define OFF_STK (OFF_VAL + (size_t)T_ * B_)
#define OFF_PTR (OFF_STK + (size_t)B_ * S_ * H_)

// x-GEMM scratch, laid out [t][b][j] so each scan block's per-step seeds are contiguous
__device__ float g_xacc[(size_t)T_ * B_ * H_];

// ===================== xgemm v4: [B*T x 64] @ x-half of W1 =====================
// 256 rows/block (grid 1024), 8-row x 8-col register tile: per warp-k the smem
// traffic is 64 B/lane for 64 lane-MACs (1 B/MAC — 4.5x less than v3).
// Per-output chain: FFMA k=0..63 ascending from 0 — bit-identical to R13/14/15.
#define XG_ROWS 256
#define XG_ST   68
#define XG_SMEM ((64 * XG_ST + XG_ROWS * XG_ST) * 4)

__global__ void __launch_bounds__(256) xgemm_kernel(
    const float* __restrict__ x, const float* __restrict__ W1,
    float* __restrict__ xacc)
{
    extern __shared__ float xsm[];
    float* Wx = xsm;                   // [k][j] stride 68
    float* xs = xsm + 64 * XG_ST;      // [r][k] stride 68

    const int tid = threadIdx.x;
    const size_t row0 = (size_t)blockIdx.x * XG_ROWS;

    // stage W1 x-half transposed (stride 68 -> 4-way max STS conflict)
    for (int i = tid; i < 4096; i += 256) {
        int k = i & 63, j = i >> 6;
        Wx[k * XG_ST + j] = W1[j * 128 + k];
    }
    // stage x [r][k], float4 STS conflict-free
    for (int i4 = tid; i4 < (XG_ROWS * 64) / 4; i4 += 256) {
        int flat = i4 * 4;
        int r = flat >> 6, k4 = flat & 63;
        *(float4*)&xs[r * XG_ST + k4] = *(const float4*)(x + (row0 + r) * 64 + k4);
    }
    __syncthreads();

    const int rg = tid >> 3;   // rows 8*rg .. 8*rg+7
    const int cg = tid & 7;    // cols 4*cg..4*cg+3  and  32+4*cg..32+4*cg+3

    u64 acc[32];               // [row-pair p][col c], c: 0-3 = half A, 4-7 = half B
    #pragma unroll
    for (int i = 0; i < 32; ++i) acc[i] = 0ull;

    const float* xb = &xs[(8 * rg) * XG_ST];
    const float* wb = &Wx[4 * cg];

    #pragma unroll 4
    for (int k = 0; k < 64; ++k) {
        // 8 rows paired into 4 fma2 inputs (lane .x = even row, .y = odd row)
        u64 in0 = pack2(xb[k],              xb[XG_ST + k]);
        u64 in1 = pack2(xb[2 * XG_ST + k],  xb[3 * XG_ST + k]);
        u64 in2 = pack2(xb[4 * XG_ST + k],  xb[5 * XG_ST + k]);
        u64 in3 = pack2(xb[6 * XG_ST + k],  xb[7 * XG_ST + k]);
        float4 wA = *(const float4*)(wb + k * XG_ST);        // cols 4cg..4cg+3
        float4 wB = *(const float4*)(wb + k * XG_ST + 32);   // cols 32+4cg..
        u64 w0 = pack2(wA.x, wA.x), w1 = pack2(wA.y, wA.y);
        u64 w2 = pack2(wA.z, wA.z), w3 = pack2(wA.w, wA.w);
        u64 w4 = pack2(wB.x, wB.x), w5 = pack2(wB.y, wB.y);
        u64 w6 = pack2(wB.z, wB.z), w7 = pack2(wB.w, wB.w);
        acc[0]  = fma2(in0, w0, acc[0]);  acc[1]  = fma2(in0, w1, acc[1]);
        acc[2]  = fma2(in0, w2, acc[2]);  acc[3]  = fma2(in0, w3, acc[3]);
        acc[4]  = fma2(in0, w4, acc[4]);  acc[5]  = fma2(in0, w5, acc[5]);
        acc[6]  = fma2(in0, w6, acc[6]);  acc[7]  = fma2(in0, w7, acc[7]);
        acc[8]  = fma2(in1, w0, acc[8]);  acc[9]  = fma2(in1, w1, acc[9]);
        acc[10] = fma2(in1, w2, acc[10]); acc[11] = fma2(in1, w3, acc[11]);
        acc[12] = fma2(in1, w4, acc[12]); acc[13] = fma2(in1, w5, acc[13]);
        acc[14] = fma2(in1, w6, acc[14]); acc[15] = fma2(in1, w7, acc[15]);
        acc[16] = fma2(in2, w0, acc[16]); acc[17] = fma2(in2, w1, acc[17]);
        acc[18] = fma2(in2, w2, acc[18]); acc[19] = fma2(in2, w3, acc[19]);
        acc[20] = fma2(in2, w4, acc[20]); acc[21] = fma2(in2, w5, acc[21]);
        acc[22] = fma2(in2, w6, acc[22]); acc[23] = fma2(in2, w7, acc[23]);
        acc[24] = fma2(in3, w0, acc[24]); acc[25] = fma2(in3, w1, acc[25]);
        acc[26] = fma2(in3, w2, acc[26]); acc[27] = fma2(in3, w3, acc[27]);
        acc[28] = fma2(in3, w4, acc[28]); acc[29] = fma2(in3, w5, acc[29]);
        acc[30] = fma2(in3, w6, acc[30]); acc[31] = fma2(in3, w7, acc[31]);
    }

    // epilogue: write to [t][b][j] layout; per row two contiguous float4s
    #pragma unroll
    for (int p = 0; p < 4; ++p) {
        float2 cA0 = unpack2(acc[p * 8 + 0]);
        float2 cA1 = unpack2(acc[p * 8 + 1]);
        float2 cA2 = unpack2(acc[p * 8 + 2]);
        float2 cA3 = unpack2(acc[p * 8 + 3]);
        float2 cB0 = unpack2(acc[p * 8 + 4]);
        float2 cB1 = unpack2(acc[p * 8 + 5]);
        float2 cB2 = unpack2(acc[p * 8 + 6]);
        float2 cB3 = unpack2(acc[p * 8 + 7]);
        size_t R0 = row0 + 8 * rg + 2 * p;       // R = b*T + t
        size_t R1 = R0 + 1;
        size_t b0 = R0 >> 6, t0 = R0 & 63;
        size_t b1 = R1 >> 6, t1 = R1 & 63;
        float* d0 = xacc + (t0 * B_ + b0) * 64;
        float* d1 = xacc + (t1 * B_ + b1) * 64;
        *(float4*)(d0 + 4 * cg)      = make_float4(cA0.x, cA1.x, cA2.x, cA3.x);
        *(float4*)(d0 + 32 + 4 * cg) = make_float4(cB0.x, cB1.x, cB2.x, cB3.x);
        *(float4*)(d1 + 4 * cg)      = make_float4(cA0.y, cA1.y, cA2.y, cA3.y);
        *(float4*)(d1 + 32 + 4 * cg) = make_float4(cB0.y, cB1.y, cB2.y, cB3.y);
    }
}

// ============================ scan kernel (R15 verbatim — 455us validated) ============================
#define SM_W1C   0                       // [64][64] c-half of W1 [k][j]
#define SM_W2T   (SM_W1C + 4096)         // [64][64]
#define SM_WHT   (SM_W2T + 4096)         // [64][12]
#define SM_B1    (SM_WHT + 768)
#define SM_B2    (SM_B1 + 64)
#define SM_BH    (SM_B2 + 64)            // 12
#define SM_CT    (SM_BH + 12)            // [64][18] top, transposed
#define SM_XT    (SM_CT + 1152)          // [64][18] xacc seeds, transposed
#define SM_HT    (SM_XT + 1152)          // [64][18]
#define SM_PT    (SM_HT + 1152)          // [64][18]
#define SM_LS    (SM_PT + 1152)          // [16][4]
#define SM_INTS  (SM_LS + 64)            // ptrS(16) + wbits(112)
#define SMEM_BYTES ((SM_INTS + 128) * 4)

__global__ void __launch_bounds__(NTHR, 2) stacknet_kernel(
    const float* __restrict__ x,        const float* __restrict__ stack_in,
    const int*   __restrict__ ptr_in,
    const float* __restrict__ W1,  const float* __restrict__ b1,
    const float* __restrict__ W2,  const float* __restrict__ b2,
    const float* __restrict__ Ws,  const float* __restrict__ bsv,
    const float* __restrict__ Wp,  const float* __restrict__ bp,
    const float* __restrict__ Wv,  const float* __restrict__ bv,
    float* __restrict__ out)
{
    extern __shared__ float sm[];
    float* W1c  = sm + SM_W1C;
    float* W2t  = sm + SM_W2T;
    float* Wht  = sm + SM_WHT;
    float* b1s  = sm + SM_B1;
    float* b2s  = sm + SM_B2;
    float* bhs  = sm + SM_BH;
    float* CT   = sm + SM_CT;
    float* XT   = sm + SM_XT;
    float* Ht   = sm + SM_HT;
    float* Pt   = sm + SM_PT;
    float* Ls   = sm + SM_LS;
    int*   ptrS  = (int*)(sm + SM_INTS);
    u32*   wbits = (u32*)(ptrS + 16);

    const int tid  = threadIdx.x;
    const int base = blockIdx.x * G_;

    for (int i = tid; i < 4096; i += NTHR) {            // c-half of W1 (k = 64..127)
        int k = i & 63, j = i >> 6;
        W1c[k * 64 + j] = W1[j * 128 + 64 + k];
    }
    for (int i = tid; i < 4096; i += NTHR) { int j = i >> 6, k = i & 63;  W2t[k * 64 + j] = W2[i]; }
    for (int i = tid; i < 192;  i += NTHR) { int h = i >> 6, k = i & 63;  Wht[k * 12 + h] = Ws[i]; }
    for (int i = tid; i < 512;  i += NTHR) { int h = 3 + (i >> 6), k = i & 63; Wht[k * 12 + h] = Wp[i]; }
    for (int i = tid; i < 64;   i += NTHR) { Wht[i * 12 + 11] = Wv[i]; }
    if (tid < 64) { b1s[tid] = b1[tid]; b2s[tid] = b2[tid]; }
    if (tid < 3)               bhs[tid] = bsv[tid];
    if (tid >= 3 && tid < 11)  bhs[tid] = bp[tid - 3];
    if (tid == 11)             bhs[11]  = bv[0];
    for (int i = tid; i < G_ * 7; i += NTHR) wbits[i] = 0;
    if (tid < G_) ptrS[tid] = ptr_in[base + tid];

    const int ep = tid & 7;
    const int cp = tid >> 3;
    const int e   = tid >> 4;
    const int seg = tid & 15;

    const size_t srow = (size_t)(base + e) * S_;
    float* ostk = out + OFF_STK;

    float4 cr, pm4, pp4, xa4;
    {
        int p0 = ptr_in[base + e];
        cr = *(const float4*)(stack_in + (srow + p0) * H_ + seg * 4);
        const float* cf = (const float*)&cr;
        xa4 = *(const float4*)(g_xacc + (size_t)(base + e) * 64 + seg * 4);  // t=0
        const float* xf = (const float*)&xa4;
        #pragma unroll
        for (int i = 0; i < 4; ++i) {
            CT[(seg * 4 + i) * 18 + e] = cf[i];
            XT[(seg * 4 + i) * 18 + e] = xf[i];
        }
    }

    for (int t = 0; t < T_; ++t) {
        __syncthreads();   // A: CT/XT(t), ptrS/wbits, prev push STG visible

        const int p = ptrS[e];
        if (t + 1 < T_) {
            const int rm = p > 0 ? p - 1 : 0;
            const int rp = p + 1;
            const float* bm = ((wbits[e * 7 + (rm >> 5)] >> (rm & 31)) & 1u) ? ostk : stack_in;
            const float* bq = ((wbits[e * 7 + (rp >> 5)] >> (rp & 31)) & 1u) ? ostk : stack_in;
            pm4 = *(const float4*)(bm + (srow + rm) * H_ + seg * 4);
            pp4 = *(const float4*)(bq + (srow + rp) * H_ + seg * 4);
            xa4 = *(const float4*)(g_xacc + ((size_t)(t + 1) * B_ + base + e) * 64 + seg * 4);
        }

        // ---- W1 (c-half): 2e x 2c tile, seeded from XT ----
        u64 a0 = *(const u64*)&XT[(2 * cp) * 18 + 2 * ep];
        u64 a1 = *(const u64*)&XT[(2 * cp + 1) * 18 + 2 * ep];
        {
            const float* inb = &CT[2 * ep];
            const float* wb  = &W1c[2 * cp];
            #pragma unroll 8
            for (int k = 0; k < 64; ++k) {
                u64 in = *(const u64*)(inb + k * 18);
                float2 w = *(const float2*)(wb + k * 64);
                a0 = fma2(in, pack2(w.x, w.x), a0);
                a1 = fma2(in, pack2(w.y, w.y), a1);
            }
        }
        {
            float2 v0 = unpack2(a0), v1 = unpack2(a1);
            int j0 = 2 * cp, e0 = 2 * ep;
            Ht[j0 * 18 + e0]           = tanh_xla(v0.x + b1s[j0]);
            Ht[j0 * 18 + e0 + 1]       = tanh_xla(v0.y + b1s[j0]);
            Ht[(j0 + 1) * 18 + e0]     = tanh_xla(v1.x + b1s[j0 + 1]);
            Ht[(j0 + 1) * 18 + e0 + 1] = tanh_xla(v1.y + b1s[j0 + 1]);
        }
        __syncthreads();   // B: Ht ready

        // ---- W2: same tile, seed 0 ----
        a0 = 0ull; a1 = 0ull;
        {
            const float* inb = &Ht[2 * ep];
            const float* wb  = &W2t[2 * cp];
            #pragma unroll 8
            for (int k = 0; k < 64; ++k) {
                u64 in = *(const u64*)(inb + k * 18);
                float2 w = *(const float2*)(wb + k * 64);
                a0 = fma2(in, pack2(w.x, w.x), a0);
                a1 = fma2(in, pack2(w.y, w.y), a1);
            }
        }
        {
            float2 v0 = unpack2(a0), v1 = unpack2(a1);
            int j0 = 2 * cp, e0 = 2 * ep;
            Pt[j0 * 18 + e0]           = tanh_xla(v0.x + b2s[j0]);
            Pt[j0 * 18 + e0 + 1]       = tanh_xla(v0.y + b2s[j0]);
            Pt[(j0 + 1) * 18 + e0]     = tanh_xla(v1.x + b2s[j0 + 1]);
            Pt[(j0 + 1) * 18 + e0 + 1] = tanh_xla(v1.y + b2s[j0 + 1]);
        }
        __syncthreads();   // C: Pt ready

        // ---- heads: 192 dots of length 64, bias LAST (R3 order) ----
        if (tid < 192) {
            int ee = tid / 12, h = tid - 12 * ee;
            float acc = 0.0f;
            #pragma unroll 8
            for (int k = 0; k < 64; ++k) acc = __fmaf_rn(Pt[k * 18 + ee], Wht[k * 12 + h], acc);
            acc += bhs[h];
            if (h < 3)       Ls[ee * 4 + h] = acc;
            else if (h < 11) out[((size_t)(base + ee) * T_ + t) * A_ + (h - 3)] = acc;
            else             out[OFF_VAL + (size_t)t * B_ + (base + ee)] = acc;
        }
        __syncthreads();   // D: Ls ready

        // ---- replicated argmax + stack update + CT/XT(t+1) ----
        {
            float l0 = Ls[e * 4], l1 = Ls[e * 4 + 1], l2 = Ls[e * 4 + 2];
            int op = 0; float bst = l0;
            if (l1 > bst) { bst = l1; op = 1; }
            if (l2 > bst) { op = 2; }
            if (seg == 0) {
                int np = p + op - 1; np = np < 0 ? 0 : np;
                ptrS[e] = np;
                if (op == 2) wbits[e * 7 + (p >> 5)] |= (1u << (p & 31));
            }
            if (op == 2) {
                float pv[4];
                #pragma unroll
                for (int i = 0; i < 4; ++i) pv[i] = Pt[(seg * 4 + i) * 18 + e];
                *(float4*)(ostk + (srow + p) * H_ + seg * 4)
                    = make_float4(pv[0], pv[1], pv[2], pv[3]);
                cr = pp4;
            } else if (op == 0) {
                cr = pm4;
            }
            if (t + 1 < T_) {
                const float* cf = (const float*)&cr;
                const float* xf = (const float*)&xa4;
                #pragma unroll
                for (int i = 0; i < 4; ++i) {
                    CT[(seg * 4 + i) * 18 + e] = cf[i];
                    XT[(seg * 4 + i) * 18 + e] = xf[i];
                }
            }
        }
    }

    __syncthreads();   // ptrS writers (seg==0) != readers below
    if (tid < G_) out[OFF_PTR + base + tid] = (float)ptrS[tid];
    __syncthreads();

    for (int it = tid; it < G_ * S_; it += NTHR) {
        int ee = it / S_, rr = it - S_ * ee;
        if (!((wbits[ee * 7 + (rr >> 5)] >> (rr & 31)) & 1u)) {
            const float4* src = (const float4*)(stack_in + ((size_t)(base + ee) * S_ + rr) * H_);
            float4* dst = (float4*)(out + OFF_STK + ((size_t)(base + ee) * S_ + rr) * H_);
            #pragma unroll
            for (int q = 0; q < 16; ++q) dst[q] = src[q];
        }
    }
}

extern "C" void kernel_launch(void* const* d_in, const int* in_sizes, int n_in,
                              void* d_out, int out_size) {
    (void)in_sizes; (void)n_in; (void)out_size;
    cudaFuncSetAttribute(stacknet_kernel, cudaFuncAttributeMaxDynamicSharedMemorySize, SMEM_BYTES);
    cudaFuncSetAttribute(xgemm_kernel, cudaFuncAttributeMaxDynamicSharedMemorySize, XG_SMEM);
    const float* x        = (const float*)d_in[0];
    const float* stack_in = (const float*)d_in[1];
    const int*   ptrs     = (const int*)  d_in[2];
    const float* W1 = (const float*)d_in[3];  const float* b1 = (const float*)d_in[4];
    const float* W2 = (const float*)d_in[5];  const float* b2 = (const float*)d_in[6];
    const float* Ws = (const float*)d_in[7];  const float* bs = (const float*)d_in[8];
    const float* Wp = (const float*)d_in[9];  const float* bp = (const float*)d_in[10];
    const float* Wv = (const float*)d_in[11]; const float* bv = (const float*)d_in[12];
    float* out = (float*)d_out;

    float* xacc = nullptr;
    cudaGetSymbolAddress((void**)&xacc, g_xacc);

    xgemm_kernel<<<(B_ * T_) / XG_ROWS, 256, XG_SMEM>>>(x, W1, xacc);
    stacknet_kernel<<<B_ / G_, NTHR, SMEM_BYTES>>>(
        x, stack_in, ptrs, W1, b1, W2, b2, Ws, bs, Wp, bp, Wv, bv, out);
}